// round 1
// baseline (speedup 1.0000x reference)
#include <cuda_runtime.h>
#include <cstdint>

#define IN_C  64
#define OUT_C 64
#define GR    4
#define CPG   16
#define DPG   16
#define KMAX  27
#define MAX_E 2000000

// ---- scratch (device globals; no allocation allowed) ----
__device__ int g_hist[KMAX];
__device__ int g_cursor[KMAX];
__device__ int g_sorted[MAX_E];

// ---- f32x2 helpers (Blackwell packed fp32, 2 FMA/instr) ----
__device__ __forceinline__ unsigned long long pack_dup(float x) {
    unsigned long long r; unsigned xi = __float_as_uint(x);
    asm("mov.b64 %0, {%1, %1};" : "=l"(r) : "r"(xi));
    return r;
}
__device__ __forceinline__ unsigned long long fma2(unsigned long long a,
                                                   unsigned long long b,
                                                   unsigned long long c) {
    unsigned long long d;
    asm("fma.rn.f32x2 %0, %1, %2, %3;" : "=l"(d) : "l"(a), "l"(b), "l"(c));
    return d;
}
__device__ __forceinline__ void unpack2(unsigned long long v, float& lo, float& hi) {
    asm("mov.b64 {%0, %1}, %2;" : "=f"(lo), "=f"(hi) : "l"(v));
}

// ---- 1) out = bias (d_out is poisoned before timing) ----
__global__ void init_out(float4* __restrict__ out, const float* __restrict__ bias, int n4) {
    __shared__ float4 b4[16];
    if (threadIdx.x < 16) b4[threadIdx.x] = reinterpret_cast<const float4*>(bias)[threadIdx.x];
    __syncthreads();
    int idx = blockIdx.x * blockDim.x + threadIdx.x;
    if (idx < n4) out[idx] = b4[idx & 15];
}

__global__ void init_meta() {
    if (threadIdx.x < KMAX) g_hist[threadIdx.x] = 0;
}

// ---- 2) histogram of k ----
__global__ void hist_k(const int* __restrict__ ka, int E) {
    __shared__ int h[KMAX];
    if (threadIdx.x < KMAX) h[threadIdx.x] = 0;
    __syncthreads();
    for (int idx = blockIdx.x * blockDim.x + threadIdx.x; idx < E;
         idx += gridDim.x * blockDim.x)
        atomicAdd(&h[ka[idx]], 1);
    __syncthreads();
    if (threadIdx.x < KMAX && h[threadIdx.x]) atomicAdd(&g_hist[threadIdx.x], h[threadIdx.x]);
}

// ---- 3) tiny exclusive scan -> cursors ----
__global__ void scan_k() {
    if (threadIdx.x == 0) {
        int s = 0;
        for (int q = 0; q < KMAX; q++) { g_cursor[q] = s; s += g_hist[q]; }
    }
}

// ---- 4) scatter edge ids into k-sorted order (block-aggregated atomics) ----
__global__ void scatter_k(const int* __restrict__ ka, int E) {
    __shared__ int cnt[KMAX];
    __shared__ int bas[KMAX];
    for (int base = blockIdx.x * blockDim.x; base < E; base += gridDim.x * blockDim.x) {
        int idx = base + threadIdx.x;
        if (threadIdx.x < KMAX) cnt[threadIdx.x] = 0;
        __syncthreads();
        int kv = 0, my = 0;
        bool v = idx < E;
        if (v) { kv = ka[idx]; my = atomicAdd(&cnt[kv], 1); }
        __syncthreads();
        if (threadIdx.x < KMAX && cnt[threadIdx.x])
            bas[threadIdx.x] = atomicAdd(&g_cursor[threadIdx.x], cnt[threadIdx.x]);
        __syncthreads();
        if (v) g_sorted[bas[kv] + my] = idx;
        __syncthreads();
    }
}

// ---- 5) fused conv: warp handles 8 edges (sorted => warp-uniform k mostly) ----
// SMEM: weights [27][4][16][16] with group-pad 4 floats (broadcast, 1-phase LDS),
//       per-warp x staging 8 rows stride 68 (conflict-free 4-phase LDS.128).
#define WGS   260                  // group stride (floats): 256 + 4 pad
#define WKS   (4 * WGS)            // 1040
#define WTOT  (KMAX * WKS)         // 28080 floats = 112320 B
#define XSTR  68                   // staged row stride (floats)
#define XWARP (8 * XSTR)           // 544 floats per warp
#define CONV_SMEM_BYTES ((WTOT + 32 * XWARP) * 4)   // 181952 B

__global__ __launch_bounds__(1024, 1) void conv_k(
    const float* __restrict__ x, const int* __restrict__ ia,
    const int* __restrict__ ja, const int* __restrict__ ka,
    const float* __restrict__ wgt, float* __restrict__ out, int E)
{
    extern __shared__ float smem[];
    float* sw = smem;
    float* sx = smem + WTOT;

    // cooperative weight load + transform: w[k][g][c][d] = weight[(g*16+c)*16+d][k]
    for (int e = threadIdx.x; e < KMAX * 1024; e += blockDim.x) {
        int kq = e >> 10;
        int r  = e & 1023;
        int g  = r >> 8;
        int c  = (r >> 4) & 15;
        int d  = r & 15;
        sw[kq * WKS + g * WGS + c * 16 + d] = wgt[((g * 16 + c) * 16 + d) * KMAX + kq];
    }
    __syncthreads();

    int lane = threadIdx.x & 31;
    int warp = threadIdx.x >> 5;
    float* sxw = sx + warp * XWARP;
    int el = lane >> 2;   // edge slot 0..7
    int gs = lane & 3;    // group 0..3

    int nB = (E + 7) >> 3;
    int gw = blockIdx.x * (blockDim.x >> 5) + warp;
    int nw = gridDim.x * (blockDim.x >> 5);

    for (int b = gw; b < nB; b += nw) {
        int base = b << 3;
        int cnt = E - base; if (cnt > 8) cnt = 8;

        // lanes 0..7 fetch this batch's edge metadata
        int jj = 0, kv = 0, iv = 0;
        if (lane < 8 && lane < cnt) {
            int eid = g_sorted[base + lane];
            jj = ja[eid];
            kv = ka[eid];
            iv = ia[eid];
        }

        // coalesced staging of 8 x-rows (2 rows / warp instr, 4 wavefronts)
        #pragma unroll
        for (int it = 0; it < 4; it++) {
            int row = 2 * it + (lane >> 4);
            int f4  = lane & 15;
            int jr  = __shfl_sync(0xffffffffu, jj, row);
            float4 v = make_float4(0.f, 0.f, 0.f, 0.f);
            if (row < cnt) v = *(const float4*)(x + (size_t)jr * IN_C + f4 * 4);
            *(float4*)(sxw + row * XSTR + f4 * 4) = v;
        }
        __syncwarp();

        int myk = __shfl_sync(0xffffffffu, kv, el);
        int myi = __shfl_sync(0xffffffffu, iv, el);

        // this lane's 16 input channels (group gs of edge el)
        const float* xp = sxw + el * XSTR + gs * CPG;
        float4 xv0 = *(const float4*)(xp + 0);
        float4 xv1 = *(const float4*)(xp + 4);
        float4 xv2 = *(const float4*)(xp + 8);
        float4 xv3 = *(const float4*)(xp + 12);
        __syncwarp();   // staging region free for next iteration after reg capture

        float xs[16];
        xs[0]=xv0.x; xs[1]=xv0.y; xs[2]=xv0.z; xs[3]=xv0.w;
        xs[4]=xv1.x; xs[5]=xv1.y; xs[6]=xv1.z; xs[7]=xv1.w;
        xs[8]=xv2.x; xs[9]=xv2.y; xs[10]=xv2.z; xs[11]=xv2.w;
        xs[12]=xv3.x; xs[13]=xv3.y; xs[14]=xv3.z; xs[15]=xv3.w;

        const float* wp = sw + myk * WKS + gs * WGS;

        unsigned long long acc[8];
        #pragma unroll
        for (int q = 0; q < 8; q++) acc[q] = 0ull;

        #pragma unroll
        for (int c = 0; c < 16; c++) {
            unsigned long long xd = pack_dup(xs[c]);
            const ulonglong2* wrow = reinterpret_cast<const ulonglong2*>(wp + c * 16);
            #pragma unroll
            for (int dq = 0; dq < 4; dq++) {
                ulonglong2 wv = wrow[dq];         // broadcast LDS.128: 4 weights
                acc[2 * dq]     = fma2(xd, wv.x, acc[2 * dq]);
                acc[2 * dq + 1] = fma2(xd, wv.y, acc[2 * dq + 1]);
            }
        }

        if (el < cnt) {
            float* op = out + (size_t)myi * OUT_C + gs * DPG;
            #pragma unroll
            for (int dq = 0; dq < 4; dq++) {
                float a0, a1, a2, a3;
                unpack2(acc[2 * dq],     a0, a1);
                unpack2(acc[2 * dq + 1], a2, a3);
                atomicAdd(reinterpret_cast<float4*>(op + dq * 4),
                          make_float4(a0, a1, a2, a3));
            }
        }
    }
}

extern "C" void kernel_launch(void* const* d_in, const int* in_sizes, int n_in,
                              void* d_out, int out_size) {
    const float* x    = (const float*)d_in[0];
    const int*   ia   = (const int*)d_in[1];
    const int*   ja   = (const int*)d_in[2];
    const int*   ka   = (const int*)d_in[3];
    // d_in[4] = n (scalar), unused: derive from sizes
    const float* wgt  = (const float*)d_in[5];
    const float* bias = (const float*)d_in[6];
    float*       out  = (float*)d_out;

    int n = in_sizes[0] / IN_C;
    int E = in_sizes[1];
    if (E > MAX_E) E = MAX_E;

    int n4 = n * (OUT_C / 4);
    init_out<<<(n4 + 255) / 256, 256>>>((float4*)out, bias, n4);
    init_meta<<<1, 32>>>();
    hist_k<<<296, 256>>>(ka, E);
    scan_k<<<1, 32>>>();
    scatter_k<<<296, 256>>>(ka, E);

    cudaFuncSetAttribute(conv_k, cudaFuncAttributeMaxDynamicSharedMemorySize,
                         CONV_SMEM_BYTES);
    conv_k<<<148, 1024, CONV_SMEM_BYTES>>>(x, ia, ja, ka, wgt, out, E);
}

// round 2
// speedup vs baseline: 1.7640x; 1.7640x over previous
#include <cuda_runtime.h>
#include <cstdint>

#define IN_C   64
#define OUT_C  64
#define KMAX   27
#define MAX_E  2000000
#define BATCH  16
#define PADCAP (MAX_E + KMAX * BATCH + BATCH)

// weight smem layout: [k][g][c][d], group stride padded so the per-c LDS.128
// (lanes = h*16 + gs*4 + dq) is bank-conflict-free in each 8-lane sub-request.
#define WGS  272                 // 256 + 16 pad ; 272 mod 32 == 16
#define WKS  (4 * WGS)           // 1088
#define WTOT (KMAX * WKS)        // 29376 floats = 117504 B

// ---- scratch (device globals; no allocation allowed) ----
__device__ int g_hist[KMAX];
__device__ int g_cursor[KMAX];
__device__ int g_sorted[PADCAP];

// ---- f32x2 helpers (packed fp32, 2 FMA/instr) ----
__device__ __forceinline__ unsigned long long pack_dup(float x) {
    unsigned long long r; unsigned xi = __float_as_uint(x);
    asm("mov.b64 %0, {%1, %1};" : "=l"(r) : "r"(xi));
    return r;
}
__device__ __forceinline__ unsigned long long fma2(unsigned long long a,
                                                   unsigned long long b,
                                                   unsigned long long c) {
    unsigned long long d;
    asm("fma.rn.f32x2 %0, %1, %2, %3;" : "=l"(d) : "l"(a), "l"(b), "l"(c));
    return d;
}
__device__ __forceinline__ void unpack2(unsigned long long v, float& lo, float& hi) {
    asm("mov.b64 {%0, %1}, %2;" : "=f"(lo), "=f"(hi) : "l"(v));
}

// ---- 1) out = bias, g_sorted = -1 (sentinels), hist = 0 ----
__global__ void init_all(float4* __restrict__ out, const float* __restrict__ bias,
                         int n4, int preN) {
    __shared__ float4 b4[16];
    if (threadIdx.x < 16) b4[threadIdx.x] = reinterpret_cast<const float4*>(bias)[threadIdx.x];
    if (blockIdx.x == 0 && threadIdx.x < KMAX) g_hist[threadIdx.x] = 0;
    __syncthreads();
    int idx = blockIdx.x * blockDim.x + threadIdx.x;
    if (idx < n4)  out[idx] = b4[idx & 15];
    if (idx < preN) g_sorted[idx] = -1;
}

// ---- 2) histogram of k ----
__global__ void hist_k(const int* __restrict__ ka, int E) {
    __shared__ int h[KMAX];
    if (threadIdx.x < KMAX) h[threadIdx.x] = 0;
    __syncthreads();
    for (int idx = blockIdx.x * blockDim.x + threadIdx.x; idx < E;
         idx += gridDim.x * blockDim.x)
        atomicAdd(&h[ka[idx]], 1);
    __syncthreads();
    if (threadIdx.x < KMAX && h[threadIdx.x]) atomicAdd(&g_hist[threadIdx.x], h[threadIdx.x]);
}

// ---- 3) warp exclusive scan of BATCH-aligned bucket sizes ----
__global__ void scan_k() {
    int lane = threadIdx.x;
    int v = (lane < KMAX) ? ((g_hist[lane] + BATCH - 1) & ~(BATCH - 1)) : 0;
    int s = v;
    #pragma unroll
    for (int o = 1; o < 32; o <<= 1) {
        int t = __shfl_up_sync(0xffffffffu, s, o);
        if (lane >= o) s += t;
    }
    if (lane < KMAX) g_cursor[lane] = s - v;   // exclusive, aligned starts
}

// ---- 4) scatter edge ids into k-sorted order (block-aggregated atomics) ----
// gaps up to the per-bucket 16-alignment stay -1 (sentinels)
__global__ void scatter_k(const int* __restrict__ ka, int E) {
    __shared__ int cnt[KMAX];
    __shared__ int bas[KMAX];
    for (int base = blockIdx.x * blockDim.x; base < E; base += gridDim.x * blockDim.x) {
        int idx = base + threadIdx.x;
        if (threadIdx.x < KMAX) cnt[threadIdx.x] = 0;
        __syncthreads();
        int kv = 0, my = 0;
        bool v = idx < E;
        if (v) { kv = ka[idx]; my = atomicAdd(&cnt[kv], 1); }
        __syncthreads();
        if (threadIdx.x < KMAX && cnt[threadIdx.x])
            bas[threadIdx.x] = atomicAdd(&g_cursor[threadIdx.x], cnt[threadIdx.x]);
        __syncthreads();
        if (v) g_sorted[bas[kv] + my] = idx;
        __syncthreads();
    }
}

// ---- 5) fused conv ----
// Warp batch = 16 edges (k-uniform by construction).
// Lane = h*16 + gs*4 + dq: owns output d-quad [4dq..4dq+3] of group gs for the
// 8 edges of half h. Weights read once per c by the whole warp (one LDS.128,
// 256B distinct). x read directly from GMEM (L1-resident within batch).
__global__ __launch_bounds__(512, 1) void conv_k(
    const float* __restrict__ x, const int* __restrict__ ia,
    const int* __restrict__ ja, const int* __restrict__ ka,
    const float* __restrict__ wgt, float* __restrict__ out, int nB)
{
    extern __shared__ float sw[];

    // cooperative weight load: src coalesced, dst scattered (once per CTA)
    for (int idx = threadIdx.x; idx < IN_C * (OUT_C / 4) * KMAX; idx += blockDim.x) {
        int k = idx % KMAX;
        int r = idx / KMAX;          // r = (g*16+c)*16 + d
        int d = r & 15;
        int c = (r >> 4) & 15;
        int g = r >> 8;
        sw[k * WKS + g * WGS + c * 16 + d] = wgt[idx];
    }
    __syncthreads();

    int lane = threadIdx.x & 31;
    int warp = threadIdx.x >> 5;
    int dq = lane & 3;
    int gs = (lane >> 2) & 3;
    int h  = lane >> 4;

    int nw = gridDim.x * (blockDim.x >> 5);

    for (int b = blockIdx.x * (blockDim.x >> 5) + warp; b < nB; b += nw) {
        int base = b * BATCH;

        // lanes 0..15 hold edge (base+lane) metadata
        int eid = -1;
        if (lane < BATCH) eid = g_sorted[base + lane];
        int jj = 0, kk = 0, ii = 0;
        if (eid >= 0) { jj = ja[eid]; kk = ka[eid]; ii = ia[eid]; }

        int kb = __shfl_sync(0xffffffffu, kk, 0);   // batch-uniform k
        const float* wp = sw + kb * WKS + gs * WGS + dq * 4;

        // this lane's 8 edge rows (half h) + validity mask
        int jr[8];
        unsigned vm = 0;
        #pragma unroll
        for (int es = 0; es < 8; es++) {
            int src = h * 8 + es;
            jr[es] = __shfl_sync(0xffffffffu, jj, src);
            int ev  = __shfl_sync(0xffffffffu, eid, src);
            if (ev >= 0) vm |= (1u << es);
        }

        ulonglong2 acc[8];
        #pragma unroll
        for (int es = 0; es < 8; es++) { acc[es].x = 0ull; acc[es].y = 0ull; }

        #pragma unroll
        for (int cq = 0; cq < 4; cq++) {
            // gather x chunks: lane reads [gs*16 + cq*4 .. +3] of each of its 8 rows
            float4 xq[8];
            #pragma unroll
            for (int es = 0; es < 8; es++) {
                float4 v = make_float4(0.f, 0.f, 0.f, 0.f);
                if (vm & (1u << es))
                    v = *(const float4*)(x + (size_t)jr[es] * IN_C + gs * 16 + cq * 4);
                xq[es] = v;
            }
            #pragma unroll
            for (int cc = 0; cc < 4; cc++) {
                int c = cq * 4 + cc;
                ulonglong2 wv = *(const ulonglong2*)(wp + c * 16);  // 1 LDS.128 / warp / c
                #pragma unroll
                for (int es = 0; es < 8; es++) {
                    float xs = (cc == 0) ? xq[es].x : (cc == 1) ? xq[es].y
                             : (cc == 2) ? xq[es].z : xq[es].w;
                    unsigned long long xd = pack_dup(xs);
                    acc[es].x = fma2(xd, wv.x, acc[es].x);
                    acc[es].y = fma2(xd, wv.y, acc[es].y);
                }
            }
        }

        // epilogue: one RED.128 per (lane, edge-slot); 2 edges per warp instr
        #pragma unroll
        for (int es = 0; es < 8; es++) {
            int ie = __shfl_sync(0xffffffffu, ii, h * 8 + es);
            if (vm & (1u << es)) {
                float a0, a1, a2, a3;
                unpack2(acc[es].x, a0, a1);
                unpack2(acc[es].y, a2, a3);
                atomicAdd(reinterpret_cast<float4*>(out + (size_t)ie * OUT_C + gs * 16 + dq * 4),
                          make_float4(a0, a1, a2, a3));
            }
        }
    }
}

extern "C" void kernel_launch(void* const* d_in, const int* in_sizes, int n_in,
                              void* d_out, int out_size) {
    const float* x    = (const float*)d_in[0];
    const int*   ia   = (const int*)d_in[1];
    const int*   ja   = (const int*)d_in[2];
    const int*   ka   = (const int*)d_in[3];
    // d_in[4] = n (scalar), unused: derive from sizes
    const float* wgt  = (const float*)d_in[5];
    const float* bias = (const float*)d_in[6];
    float*       out  = (float*)d_out;

    int n = in_sizes[0] / IN_C;
    int E = in_sizes[1];
    if (E > MAX_E) E = MAX_E;

    int n4   = n * (OUT_C / 4);
    int preN = E + KMAX * BATCH;                 // sentinel prefill range
    int nB   = (preN + BATCH - 1) / BATCH;       // >= padded_total / BATCH
    if (nB * BATCH > preN) preN = nB * BATCH;

    int initN  = (n4 > preN) ? n4 : preN;
    init_all<<<(initN + 255) / 256, 256>>>((float4*)out, bias, n4, preN);
    hist_k<<<296, 256>>>(ka, E);
    scan_k<<<1, 32>>>();
    scatter_k<<<296, 256>>>(ka, E);

    cudaFuncSetAttribute(conv_k, cudaFuncAttributeMaxDynamicSharedMemorySize,
                         WTOT * 4);
    conv_k<<<148, 512, WTOT * 4>>>(x, ia, ja, ka, wgt, out, nB);
}